// round 1
// baseline (speedup 1.0000x reference)
#include <cuda_runtime.h>
#include <math_constants.h>

#define BATCH 2
#define NP    4096
#define NQ    16384
#define FDIM  448            // 64 + 128 + 256
#define AGGP  720            // 707 padded to multiple of 16
#define NPTS  (BATCH * NQ)   // 32768 total query points

// ---------------- scratch (device globals; no allocation allowed) ----------
__device__ float g_f1[BATCH * 64 * NP];        // channel-major
__device__ float g_f2[BATCH * 128 * NP];       // channel-major
__device__ float g_fall[BATCH * NP * FDIM];    // point-major (f1|f2|f3)
__device__ int   g_gmax[BATCH * 256];          // global max (as int bits, vals>=0)
__device__ int   g_knni[NPTS * 3];
__device__ float g_knnw[NPTS * 3];
__device__ float g_r1p[256 * AGGP];            // zero-padded r1 weights
__device__ float g_agg[NPTS * AGGP];
__device__ float g_h1[NPTS * 256];
__device__ float g_h2[NPTS * 128];
__device__ float g_h3[NPTS * 64];

// ---------------- feature extractor -----------------------------------------
__global__ void mlp1_kernel(const float* __restrict__ op,
                            const float* __restrict__ w1,
                            const float* __restrict__ b1) {
    int tid = blockIdx.x * blockDim.x + threadIdx.x;   // over BATCH*64*NP
    int pt = tid & (NP - 1);
    int c  = (tid >> 12) & 63;
    int b  = tid >> 18;
    float x = op[b * 3 * NP + 0 * NP + pt];
    float y = op[b * 3 * NP + 1 * NP + pt];
    float z = op[b * 3 * NP + 2 * NP + pt];
    float v = b1[c] + w1[c * 3 + 0] * x + w1[c * 3 + 1] * y + w1[c * 3 + 2] * z;
    v = fmaxf(v, 0.0f);
    g_f1[tid] = v;
    g_fall[(b * NP + pt) * FDIM + c] = v;
}

__global__ void mlp2_kernel(const float* __restrict__ w2,
                            const float* __restrict__ b2) {
    int tid = blockIdx.x * blockDim.x + threadIdx.x;   // over BATCH*128*NP
    int pt = tid & (NP - 1);
    int c  = (tid >> 12) & 127;
    int b  = tid >> 19;
    const float* f1 = g_f1 + b * 64 * NP + pt;
    const float* w  = w2 + c * 64;
    float v = b2[c];
#pragma unroll 8
    for (int k = 0; k < 64; k++) v = fmaf(w[k], f1[k * NP], v);
    v = fmaxf(v, 0.0f);
    g_f2[tid] = v;
    g_fall[(b * NP + pt) * FDIM + 64 + c] = v;
}

__global__ void mlp3_kernel(const float* __restrict__ w3,
                            const float* __restrict__ b3) {
    int tid = blockIdx.x * blockDim.x + threadIdx.x;   // over BATCH*256*NP
    int pt = tid & (NP - 1);
    int c  = (tid >> 12) & 255;
    int b  = tid >> 20;
    const float* f2 = g_f2 + b * 128 * NP + pt;
    const float* w  = w3 + c * 128;
    float v = b3[c];
#pragma unroll 8
    for (int k = 0; k < 128; k++) v = fmaf(w[k], f2[k * NP], v);
    v = fmaxf(v, 0.0f);
    g_fall[(b * NP + pt) * FDIM + 192 + c] = v;
    // warp max (same (b,c) within warp since NP%32==0), then atomic
    int iv = __reduce_max_sync(0xffffffffu, __float_as_int(v));
    if ((threadIdx.x & 31) == 0) atomicMax(&g_gmax[b * 256 + c], iv);
}

__global__ void zero_gmax_kernel() {
    int t = threadIdx.x + blockIdx.x * blockDim.x;
    if (t < BATCH * 256) g_gmax[t] = 0;   // relu outputs >= 0, so 0 is the identity
}

__global__ void pad_r1_kernel(const float* __restrict__ r1) {
    int tid = blockIdx.x * blockDim.x + threadIdx.x;   // over 256*AGGP
    if (tid >= 256 * AGGP) return;
    int r = tid / AGGP, k = tid - r * AGGP;
    g_r1p[tid] = (k < 707) ? r1[r * 707 + k] : 0.0f;
}

// ---------------- KNN (top-3) ------------------------------------------------
__global__ void __launch_bounds__(256) knn_kernel(const float* __restrict__ op,
                                                  const float* __restrict__ qp) {
    __shared__ float sx[NP];
    __shared__ float sy[NP];
    __shared__ float sz[NP];
    int b = blockIdx.y;
    int tid = threadIdx.x;
    for (int i = tid; i < NP; i += 256) {
        sx[i] = op[b * 3 * NP + 0 * NP + i];
        sy[i] = op[b * 3 * NP + 1 * NP + i];
        sz[i] = op[b * 3 * NP + 2 * NP + i];
    }
    __syncthreads();

    int q = blockIdx.x * 256 + tid;
    float qx = qp[b * 3 * NQ + 0 * NQ + q];
    float qy = qp[b * 3 * NQ + 1 * NQ + q];
    float qz = qp[b * 3 * NQ + 2 * NQ + q];

    float d0 = CUDART_INF_F, d1 = CUDART_INF_F, d2 = CUDART_INF_F;
    int i0 = 0, i1 = 0, i2 = 0;
#pragma unroll 4
    for (int j = 0; j < NP; j++) {
        float dx = sx[j] - qx;
        float dy = sy[j] - qy;
        float dz = sz[j] - qz;
        float d = fmaf(dx, dx, fmaf(dy, dy, dz * dz));
        if (d < d2) {
            if (d < d1) {
                d2 = d1; i2 = i1;
                if (d < d0) { d1 = d0; i1 = i0; d0 = d; i0 = j; }
                else        { d1 = d;  i1 = j; }
            } else { d2 = d; i2 = j; }
        }
    }
    // weights per reference: dist = sqrt(sum diff^2); w = (1/(dist+1e-8)) / sum
    int   ii[3] = {i0, i1, i2};
    float rc[3];
    float s = 0.0f;
#pragma unroll
    for (int k = 0; k < 3; k++) {
        float dx = sx[ii[k]] - qx;
        float dy = sy[ii[k]] - qy;
        float dz = sz[ii[k]] - qz;
        float dist = sqrtf(fmaf(dx, dx, fmaf(dy, dy, dz * dz)));
        rc[k] = 1.0f / (dist + 1e-8f);
        s += rc[k];
    }
    float inv = 1.0f / s;
    int base = (b * NQ + q) * 3;
#pragma unroll
    for (int k = 0; k < 3; k++) {
        g_knni[base + k] = ii[k];
        g_knnw[base + k] = rc[k] * inv;
    }
}

// ---------------- interp + concat into agg (warp per query) ------------------
__global__ void __launch_bounds__(256) agg_kernel(const float* __restrict__ qp) {
    int warp = blockIdx.x * 8 + (threadIdx.x >> 5);   // 0..NPTS-1
    int lane = threadIdx.x & 31;
    int b  = warp >> 14;
    int qi = warp & (NQ - 1);

    int   ik = 0; float wk = 0.0f;
    if (lane < 3) { ik = g_knni[warp * 3 + lane]; wk = g_knnw[warp * 3 + lane]; }
    int   ia = __shfl_sync(0xffffffffu, ik, 0);
    int   ib = __shfl_sync(0xffffffffu, ik, 1);
    int   ic = __shfl_sync(0xffffffffu, ik, 2);
    float wa = __shfl_sync(0xffffffffu, wk, 0);
    float wb = __shfl_sync(0xffffffffu, wk, 1);
    float wc = __shfl_sync(0xffffffffu, wk, 2);

    const float* fa = g_fall + (b * NP + ia) * FDIM;
    const float* fb = g_fall + (b * NP + ib) * FDIM;
    const float* fc = g_fall + (b * NP + ic) * FDIM;
    float* ar = g_agg + (size_t)warp * AGGP;

    if (lane < 3) ar[lane] = qp[b * 3 * NQ + lane * NQ + qi];
#pragma unroll
    for (int c = lane; c < FDIM; c += 32)
        ar[3 + c] = wa * fa[c] + wb * fb[c] + wc * fc[c];
#pragma unroll
    for (int c = lane; c < 256; c += 32)
        ar[451 + c] = __int_as_float(g_gmax[b * 256 + c]);
    if (lane < 13) ar[707 + lane] = 0.0f;   // K padding
}

// ---------------- tiled SGEMM-NT: C[m][n] = act(bias[n] + sum_k A[m][k]W[n][k])
// BM=128, BN=64, BK=16, TM=8, TN=4, 256 threads
template <bool RELU>
__global__ void __launch_bounds__(256) gemm_nt(const float* __restrict__ A, int lda,
                                               const float* __restrict__ W, int ldw,
                                               const float* __restrict__ bias,
                                               float* __restrict__ C, int ldc, int K) {
    __shared__ float As[16][132];
    __shared__ float Ws[16][68];
    const int t  = threadIdx.x;
    const int m0 = blockIdx.y * 128;
    const int n0 = blockIdx.x * 64;
    const int tx = t & 15;     // n group
    const int ty = t >> 4;     // m group

    float acc[8][4];
#pragma unroll
    for (int i = 0; i < 8; i++)
#pragma unroll
        for (int j = 0; j < 4; j++) acc[i][j] = 0.0f;

    for (int k0 = 0; k0 < K; k0 += 16) {
        // stage A tile: 128x16 = 512 float4, 2 per thread
#pragma unroll
        for (int u = 0; u < 2; u++) {
            int f4  = t * 2 + u;
            int row = f4 >> 2;
            int kc  = (f4 & 3) * 4;
            float4 v = *(const float4*)(A + (size_t)(m0 + row) * lda + k0 + kc);
            As[kc + 0][row] = v.x; As[kc + 1][row] = v.y;
            As[kc + 2][row] = v.z; As[kc + 3][row] = v.w;
        }
        // stage W tile: 64x16 = 256 float4, 1 per thread
        {
            int row = t >> 2;
            int kc  = (t & 3) * 4;
            float4 v = *(const float4*)(W + (size_t)(n0 + row) * ldw + k0 + kc);
            Ws[kc + 0][row] = v.x; Ws[kc + 1][row] = v.y;
            Ws[kc + 2][row] = v.z; Ws[kc + 3][row] = v.w;
        }
        __syncthreads();
#pragma unroll
        for (int kk = 0; kk < 16; kk++) {
            float4 a0 = *(const float4*)&As[kk][ty * 8];
            float4 a1 = *(const float4*)&As[kk][ty * 8 + 4];
            float4 w0 = *(const float4*)&Ws[kk][tx * 4];
            float a[8] = {a0.x, a0.y, a0.z, a0.w, a1.x, a1.y, a1.z, a1.w};
            float w[4] = {w0.x, w0.y, w0.z, w0.w};
#pragma unroll
            for (int i = 0; i < 8; i++)
#pragma unroll
                for (int j = 0; j < 4; j++) acc[i][j] = fmaf(a[i], w[j], acc[i][j]);
        }
        __syncthreads();
    }

    float bb[4];
#pragma unroll
    for (int j = 0; j < 4; j++) bb[j] = bias[n0 + tx * 4 + j];
#pragma unroll
    for (int i = 0; i < 8; i++) {
        float4 r;
        r.x = acc[i][0] + bb[0]; r.y = acc[i][1] + bb[1];
        r.z = acc[i][2] + bb[2]; r.w = acc[i][3] + bb[3];
        if (RELU) {
            r.x = fmaxf(r.x, 0.0f); r.y = fmaxf(r.y, 0.0f);
            r.z = fmaxf(r.z, 0.0f); r.w = fmaxf(r.w, 0.0f);
        }
        *(float4*)(C + (size_t)(m0 + ty * 8 + i) * ldc + n0 + tx * 4) = r;
    }
}

// ---------------- final layer: 64 -> 1 ---------------------------------------
__global__ void __launch_bounds__(256) final_kernel(const float* __restrict__ r4,
                                                    const float* __restrict__ rb4,
                                                    float* __restrict__ out) {
    __shared__ float s4[64];
    if (threadIdx.x < 64) s4[threadIdx.x] = r4[threadIdx.x];
    __syncthreads();
    int i = blockIdx.x * 256 + threadIdx.x;
    const float4* hp = (const float4*)(g_h3 + (size_t)i * 64);
    float acc = 0.0f;
#pragma unroll
    for (int j = 0; j < 16; j++) {
        float4 v = hp[j];
        acc += v.x * s4[4 * j + 0] + v.y * s4[4 * j + 1]
             + v.z * s4[4 * j + 2] + v.w * s4[4 * j + 3];
    }
    out[i] = acc + rb4[0];
}

// ---------------- launch -----------------------------------------------------
extern "C" void kernel_launch(void* const* d_in, const int* in_sizes, int n_in,
                              void* d_out, int out_size) {
    const float* op  = (const float*)d_in[0];
    const float* qp  = (const float*)d_in[1];
    const float* w1  = (const float*)d_in[2];
    const float* b1  = (const float*)d_in[3];
    const float* w2  = (const float*)d_in[4];
    const float* b2  = (const float*)d_in[5];
    const float* w3  = (const float*)d_in[6];
    const float* b3  = (const float*)d_in[7];
    const float* r1  = (const float*)d_in[8];
    const float* rb1 = (const float*)d_in[9];
    const float* r2  = (const float*)d_in[10];
    const float* rb2 = (const float*)d_in[11];
    const float* r3  = (const float*)d_in[12];
    const float* rb3 = (const float*)d_in[13];
    const float* r4  = (const float*)d_in[14];
    const float* rb4 = (const float*)d_in[15];
    float* out = (float*)d_out;

    float *p_h1, *p_h2, *p_h3, *p_agg, *p_r1p;
    cudaGetSymbolAddress((void**)&p_h1,  g_h1);
    cudaGetSymbolAddress((void**)&p_h2,  g_h2);
    cudaGetSymbolAddress((void**)&p_h3,  g_h3);
    cudaGetSymbolAddress((void**)&p_agg, g_agg);
    cudaGetSymbolAddress((void**)&p_r1p, g_r1p);

    // feature extractor
    zero_gmax_kernel<<<2, 256>>>();
    mlp1_kernel<<<(BATCH * 64 * NP) / 256, 256>>>(op, w1, b1);
    mlp2_kernel<<<(BATCH * 128 * NP) / 256, 256>>>(w2, b2);
    mlp3_kernel<<<(BATCH * 256 * NP) / 256, 256>>>(w3, b3);

    // knn + interpolation
    knn_kernel<<<dim3(NQ / 256, BATCH), 256>>>(op, qp);
    pad_r1_kernel<<<(256 * AGGP + 255) / 256, 256>>>(r1);
    agg_kernel<<<NPTS / 8, 256>>>(qp);

    // regressor
    gemm_nt<true ><<<dim3(256 / 64, NPTS / 128), 256>>>(p_agg, AGGP, p_r1p, AGGP, rb1, p_h1, 256, AGGP);
    gemm_nt<true ><<<dim3(128 / 64, NPTS / 128), 256>>>(p_h1, 256, r2, 256, rb2, p_h2, 128, 256);
    gemm_nt<true ><<<dim3( 64 / 64, NPTS / 128), 256>>>(p_h2, 128, r3, 128, rb3, p_h3, 64, 128);
    final_kernel<<<NPTS / 256, 256>>>(r4, rb4, out);
}